// round 16
// baseline (speedup 1.0000x reference)
#include <cuda_runtime.h>
#include <cuda_fp16.h>
#include <cstdint>

#define N_MAX 100000
#define E_MAX 1600000
#define C 64
#define NEG_SLOPE 0.2f
#define EPS 1e-16f
#define SCHUNK 1024
#define HB 1024          // hist blocks co-launched with gemm

// Scratch (no device allocation allowed)
__device__ __half2 gx_h2[(size_t)N_MAX * (C / 2)];
__device__ float   gx_asrc[N_MAX];
__device__ float   gx_adst[N_MAX];
__device__ int2    gx_se[E_MAX + 4];     // sorted-by-dst: {src, e_bits} (+pad)
__device__ int     gx_cnt[N_MAX];        // degree histogram
__device__ int     gx_off[N_MAX];        // excl prefix; destroyed by reorder cursor
__device__ int     gx_bsum[128];
__device__ int     gx_is64;

// 1) detect dtype (block 0) + zero counts (all blocks)
__global__ void kq_init(const int* __restrict__ ei_raw, int N) {
    if (blockIdx.x == 0) {
        __shared__ int nz[256];
        int t = threadIdx.x;
        int acc = 0;
        for (int k = t; k < 2048; k += 256) acc |= ei_raw[2 * k + 1];
        nz[t] = acc;
        __syncthreads();
        for (int s = 128; s > 0; s >>= 1) {
            if (t < s) nz[t] |= nz[t + s];
            __syncthreads();
        }
        if (t == 0) gx_is64 = (nz[0] == 0) ? 1 : 0;
    }
    for (int i = blockIdx.x * blockDim.x + threadIdx.x; i < N;
         i += gridDim.x * blockDim.x)
        gx_cnt[i] = 0;
}

// 2) fused: blocks [0,HB) histogram dst; blocks [HB, HB+gemmBlocks) gemm tiles
__global__ __launch_bounds__(256) void kq_gemm_hist(
    const float* __restrict__ x, const float* __restrict__ W,
    const float* __restrict__ att_src, const float* __restrict__ att_dst,
    const int* __restrict__ ei, int E, int N)
{
    __shared__ float Ws[C * C];
    __shared__ float xs[32 * C];
    __shared__ float part[32][2][2];

    if (blockIdx.x < HB) {
        int is64 = gx_is64;
        int tid0 = blockIdx.x * blockDim.x + threadIdx.x;
        int stride = HB * blockDim.x;
        if (!is64) {
            const int4* dst4 = (const int4*)(ei + E);
            int E4 = E >> 2;
            for (int i = tid0; i < E4; i += stride) {
                int4 d4 = dst4[i];
                int d0 = ((unsigned)d4.x < (unsigned)N) ? d4.x : 0;
                int d1 = ((unsigned)d4.y < (unsigned)N) ? d4.y : 0;
                int d2 = ((unsigned)d4.z < (unsigned)N) ? d4.z : 0;
                int d3 = ((unsigned)d4.w < (unsigned)N) ? d4.w : 0;
                atomicAdd(&gx_cnt[d0], 1);
                atomicAdd(&gx_cnt[d1], 1);
                atomicAdd(&gx_cnt[d2], 1);
                atomicAdd(&gx_cnt[d3], 1);
            }
            for (int i = (E4 << 2) + tid0; i < E; i += stride) {
                int d = ei[E + i];
                d = ((unsigned)d < (unsigned)N) ? d : 0;
                atomicAdd(&gx_cnt[d], 1);
            }
        } else {
            const long long* el = (const long long*)ei;
            for (int i = tid0; i < E; i += stride) {
                int d = (int)el[E + i];
                d = ((unsigned)d < (unsigned)N) ? d : 0;
                atomicAdd(&gx_cnt[d], 1);
            }
        }
        return;
    }

    int gb = blockIdx.x - HB;
    int tid  = threadIdx.x;
    int lane = tid & 31;
    int half = (tid >> 5) & 1;
    int rq   = tid >> 6;
    int col  = half * 32 + lane;

    for (int i = tid; i < C * C; i += 256) Ws[i] = W[i];
    int row0 = gb * 32;
    int nrows = min(32, N - row0);
    if (nrows <= 0) return;
    for (int i = tid; i < nrows * C; i += 256) xs[i] = x[(size_t)row0 * C + i];
    __syncthreads();

    float as = att_src[col];
    float ad = att_dst[col];
    for (int r = rq; r < nrows; r += 4) {
        float acc = 0.0f;
        #pragma unroll
        for (int k = 0; k < C; k++)
            acc = fmaf(xs[r * C + k], Ws[k * C + col], acc);
        float nb = __shfl_down_sync(0xffffffffu, acc, 1);
        if ((lane & 1) == 0)
            gx_h2[(size_t)(row0 + r) * (C / 2) + (col >> 1)] =
                __floats2half2_rn(acc, nb);
        float ps = acc * as;
        float pd = acc * ad;
        #pragma unroll
        for (int off = 16; off > 0; off >>= 1) {
            ps += __shfl_down_sync(0xffffffffu, ps, off);
            pd += __shfl_down_sync(0xffffffffu, pd, off);
        }
        if (lane == 0) { part[r][half][0] = ps; part[r][half][1] = pd; }
    }
    __syncthreads();
    if (tid < nrows) {
        gx_asrc[row0 + tid] = part[tid][0][0] + part[tid][1][0];
        gx_adst[row0 + tid] = part[tid][0][1] + part[tid][1][1];
    }
}

// 3a) per-block sums of counts
__global__ __launch_bounds__(256) void kq_scanA(int N) {
    __shared__ int sh[256];
    int t = threadIdx.x;
    int base = blockIdx.x * SCHUNK + t * 4;
    int s = 0;
    #pragma unroll
    for (int k = 0; k < 4; k++) {
        int i = base + k;
        if (i < N) s += gx_cnt[i];
    }
    sh[t] = s;
    __syncthreads();
    for (int o = 128; o > 0; o >>= 1) {
        if (t < o) sh[t] += sh[t + o];
        __syncthreads();
    }
    if (t == 0) gx_bsum[blockIdx.x] = sh[0];
}

// 3b) fused scanB+C
__global__ __launch_bounds__(256) void kq_scanC(int N, int NB) {
    __shared__ int bs[128];
    __shared__ int sh[256];
    int t = threadIdx.x;
    if (t < 128) bs[t] = (t < NB) ? gx_bsum[t] : 0;
    __syncthreads();
    for (int o = 1; o < 128; o <<= 1) {
        int u = (t < 128 && t >= o) ? bs[t - o] : 0;
        __syncthreads();
        if (t < 128) bs[t] += u;
        __syncthreads();
    }
    int base0 = (blockIdx.x == 0) ? 0 : bs[blockIdx.x - 1];

    int base = blockIdx.x * SCHUNK + t * 4;
    int c[4];
    int s = 0;
    #pragma unroll
    for (int k = 0; k < 4; k++) {
        int i = base + k;
        c[k] = (i < N) ? gx_cnt[i] : 0;
        s += c[k];
    }
    sh[t] = s;
    __syncthreads();
    for (int o = 1; o < 256; o <<= 1) {
        int u = (t >= o) ? sh[t - o] : 0;
        __syncthreads();
        sh[t] += u;
        __syncthreads();
    }
    int excl = base0 + sh[t] - s;
    #pragma unroll
    for (int k = 0; k < 4; k++) {
        int i = base + k;
        if (i < N) {
            gx_off[i] = excl;
            excl += c[k];
        }
    }
}

// 4) reorder: logit -> exp, claim slot via destructive cursor on gx_off[d]
__global__ __launch_bounds__(256) void kq_reorder(
    const int* __restrict__ ei, int E, int N)
{
    int is64 = gx_is64;
    if (!is64) {
        const int4* src4 = (const int4*)ei;
        const int4* dst4 = (const int4*)(ei + E);
        int E4 = E >> 2;
        for (int i = blockIdx.x * blockDim.x + threadIdx.x; i < E4;
             i += gridDim.x * blockDim.x) {
            int4 s4 = src4[i];
            int4 d4 = dst4[i];
            int ss[4] = {s4.x, s4.y, s4.z, s4.w};
            int dd[4] = {d4.x, d4.y, d4.z, d4.w};
            #pragma unroll
            for (int k = 0; k < 4; k++) {
                int s = ((unsigned)ss[k] < (unsigned)N) ? ss[k] : 0;
                int d = ((unsigned)dd[k] < (unsigned)N) ? dd[k] : 0;
                float v = gx_asrc[s] + gx_adst[d];
                v = (v > 0.0f) ? v : NEG_SLOPE * v;
                float ex = __expf(v);
                int p = atomicAdd(&gx_off[d], 1);
                gx_se[p] = make_int2(s, __float_as_int(ex));
            }
        }
        for (int i = (E4 << 2) + blockIdx.x * blockDim.x + threadIdx.x; i < E;
             i += gridDim.x * blockDim.x) {
            int s = ei[i], d = ei[E + i];
            s = ((unsigned)s < (unsigned)N) ? s : 0;
            d = ((unsigned)d < (unsigned)N) ? d : 0;
            float v = gx_asrc[s] + gx_adst[d];
            v = (v > 0.0f) ? v : NEG_SLOPE * v;
            float ex = __expf(v);
            int p = atomicAdd(&gx_off[d], 1);
            gx_se[p] = make_int2(s, __float_as_int(ex));
        }
    } else {
        const long long* el = (const long long*)ei;
        for (int i = blockIdx.x * blockDim.x + threadIdx.x; i < E;
             i += gridDim.x * blockDim.x) {
            int s = (int)el[i], d = (int)el[E + i];
            s = ((unsigned)s < (unsigned)N) ? s : 0;
            d = ((unsigned)d < (unsigned)N) ? d : 0;
            float v = gx_asrc[s] + gx_adst[d];
            v = (v > 0.0f) ? v : NEG_SLOPE * v;
            float ex = __expf(v);
            int p = atomicAdd(&gx_off[d], 1);
            gx_se[p] = make_int2(s, __float_as_int(ex));
        }
    }
}

// 5) gather: one warp per dst; 4-edge unrolled (MLP=4), fused denom,
//    out = tanh((Σ e·h)/(Σ e + EPS) + bias). Segment = [off[d-1], off[d]).
__global__ __launch_bounds__(256) void kq_gather(
    float* __restrict__ out, const float* __restrict__ bias, int N)
{
    int warp = (blockIdx.x * blockDim.x + threadIdx.x) >> 5;
    int lane = threadIdx.x & 31;
    if (warp >= N) return;
    int beg = (warp == 0) ? 0 : gx_off[warp - 1];
    int end = gx_off[warp];

    float ds = 0.0f;
    float2 acc = make_float2(0.0f, 0.0f);
    int j = beg;

    // peel one edge if beg is odd so int4 loads are 16B-aligned
    if ((j & 1) && j < end) {
        int2 se = gx_se[j];
        float e = __int_as_float(se.y);
        ds += e;
        float2 hv = __half22float2(gx_h2[(size_t)se.x * (C / 2) + lane]);
        acc.x = fmaf(e, hv.x, acc.x);
        acc.y = fmaf(e, hv.y, acc.y);
        j++;
    }

    // 4 edges per iteration: 2 independent int4 loads + 4 independent h loads
    for (; j + 3 < end; j += 4) {
        int4 pA = *(const int4*)&gx_se[j];       // {s0,e0,s1,e1}
        int4 pB = *(const int4*)&gx_se[j + 2];   // {s2,e2,s3,e3}
        float e0 = __int_as_float(pA.y);
        float e1 = __int_as_float(pA.w);
        float e2 = __int_as_float(pB.y);
        float e3 = __int_as_float(pB.w);
        float2 h0 = __half22float2(gx_h2[(size_t)pA.x * (C / 2) + lane]);
        float2 h1 = __half22float2(gx_h2[(size_t)pA.z * (C / 2) + lane]);
        float2 h2 = __half22float2(gx_h2[(size_t)pB.x * (C / 2) + lane]);
        float2 h3 = __half22float2(gx_h2[(size_t)pB.z * (C / 2) + lane]);
        ds += (e0 + e1) + (e2 + e3);
        acc.x = fmaf(e0, h0.x, acc.x);  acc.y = fmaf(e0, h0.y, acc.y);
        acc.x = fmaf(e1, h1.x, acc.x);  acc.y = fmaf(e1, h1.y, acc.y);
        acc.x = fmaf(e2, h2.x, acc.x);  acc.y = fmaf(e2, h2.y, acc.y);
        acc.x = fmaf(e3, h3.x, acc.x);  acc.y = fmaf(e3, h3.y, acc.y);
    }
    for (; j < end; j++) {
        int2 se = gx_se[j];
        float e = __int_as_float(se.y);
        ds += e;
        float2 hv = __half22float2(gx_h2[(size_t)se.x * (C / 2) + lane]);
        acc.x = fmaf(e, hv.x, acc.x);
        acc.y = fmaf(e, hv.y, acc.y);
    }
    float inv = 1.0f / (ds + EPS);
    float2 r;
    r.x = tanhf(fmaf(acc.x, inv, bias[lane * 2 + 0]));
    r.y = tanhf(fmaf(acc.y, inv, bias[lane * 2 + 1]));
    *(float2*)&out[(size_t)warp * C + lane * 2] = r;
}

extern "C" void kernel_launch(void* const* d_in, const int* in_sizes, int n_in,
                              void* d_out, int out_size)
{
    const float* x       = (const float*)d_in[0];
    const int*   ei      = (const int*)d_in[1];
    const float* W       = (const float*)d_in[2];
    const float* att_src = (const float*)d_in[3];
    const float* att_dst = (const float*)d_in[4];
    const float* bias    = (const float*)d_in[5];
    float* out = (float*)d_out;

    int N = in_sizes[0] / C;
    int E = in_sizes[1] / 2;

    int gridN  = (N + 255) / 256;
    int gemmB  = (N + 31) / 32;
    int gridE4 = (E / 4 + 255) / 256;
    int NB = (N + SCHUNK - 1) / SCHUNK;

    kq_init<<<gridN, 256>>>(ei, N);
    kq_gemm_hist<<<HB + gemmB, 256>>>(x, W, att_src, att_dst, ei, E, N);
    kq_scanA<<<NB, 256>>>(N);
    kq_scanC<<<NB, 256>>>(N, NB);
    kq_reorder<<<gridE4, 256>>>(ei, E, N);
    kq_gather<<<(N * 32 + 255) / 256, 256>>>(out, bias, N);
}